// round 10
// baseline (speedup 1.0000x reference)
#include <cuda_runtime.h>
#include <cuda_bf16.h>
#include <mma.h>
#include <math.h>
#include <stdint.h>

using namespace nvcuda;

#define NN 50000
#define NE 800000
#define NDIM 8
#define EDIM 3
#define HID 256
#define NHEADS 4
#define HD 64
#define NLAYERS 3
#define NG 64
#define NEG_SLOPE 0.2f

// ---------------- scratch (device globals; no allocation allowed) ----------------
__device__ float g_bufA[NN * HID];
__device__ float g_bufB[NN * HID];
__device__ float g_hp[NN * HID];
__device__ float g_logit[NE * NHEADS];   // raw leaky-relu'd logits (alpha computed in aggregate)
__device__ float g_ssrc[NN * NHEADS];
__device__ float g_sdst[NN * NHEADS];
__device__ float g_m[NN * NHEADS];
__device__ float g_invden[NN * NHEADS];
__device__ int   g_rowstart[NN + 1];
__device__ int   g_cursor[NN];
__device__ int   g_perm[NE];
__device__ int   g_part[64];
__device__ float g_coef[EDIM * NHEADS];
__device__ int   g_gstart[NG + 1];
__device__ __nv_bfloat16 g_Wh[HID * HID];
__device__ __nv_bfloat16 g_Wl[HID * HID];

__device__ __forceinline__ float* selbuf(int s) { return s ? g_bufB : g_bufA; }
__device__ __forceinline__ float elu(float x) { return x > 0.f ? x : expf(x) - 1.f; }

// ---------------- W -> bf16 hi/lo split (once per layer) ----------------
__global__ void k_wsplit(const float* __restrict__ W) {
    int i = blockIdx.x * blockDim.x + threadIdx.x;
    if (i >= HID * HID) return;
    float w = W[i];
    __nv_bfloat16 h = __float2bfloat16(w);
    g_Wh[i] = h;
    g_Wl[i] = __float2bfloat16(w - __bfloat162float(h));
}

// ================= wmma bf16-split GEMM: g_hp = selbuf(asel) @ W + bias =================
// Block: 64 rows x 128 cols, 4 warps (2x2), each warp 32x64 (8 acc frags).
#define GM 64
#define GN 128
#define APAD 24    // 48B stride
#define BPAD 136   // 272B stride

__global__ void __launch_bounds__(128, 4) k_wmma_gemm(int asel, const float* __restrict__ bias) {
    const float* A = selbuf(asel);
    __shared__ __nv_bfloat16 Ah[GM * APAD], Al[GM * APAD];
    __shared__ __nv_bfloat16 Bh[16 * BPAD], Bl[16 * BPAD];
    __shared__ float biasT[16 * GN];

    int tid = threadIdx.x;
    int wid = tid >> 5;
    int wm = wid >> 1;           // 0..1 -> 32-row slab
    int wn = wid & 1;            // 0..1 -> 64-col slab
    int bm = blockIdx.x * GM;
    int bn = blockIdx.y * GN;

    for (int i = tid; i < 16 * GN; i += 128) biasT[i] = bias[bn + (i & (GN - 1))];
    __syncthreads();

    wmma::fragment<wmma::accumulator, 16, 16, 16, float> acc[2][4];
#pragma unroll
    for (int i = 0; i < 2; i++)
#pragma unroll
        for (int j = 0; j < 4; j++)
            wmma::load_matrix_sync(acc[i][j], &biasT[wn * 64 + j * 16], GN, wmma::mem_row_major);

    for (int k0 = 0; k0 < HID; k0 += 16) {
        // ---- A tile 64x16 fp32 -> bf16 hi/lo: row = tid>>1, 8 cols each
        {
            int row = tid >> 1;
            int cq = (tid & 1) << 3;
            int gr = bm + row;
            float4 v0 = make_float4(0.f, 0.f, 0.f, 0.f), v1 = v0;
            if (gr < NN) {
                const float* ap = A + (size_t)gr * HID + k0 + cq;
                v0 = *(const float4*)ap;
                v1 = *(const float4*)(ap + 4);
            }
            __nv_bfloat16 hh[8], ll[8];
            float vv[8] = {v0.x, v0.y, v0.z, v0.w, v1.x, v1.y, v1.z, v1.w};
#pragma unroll
            for (int q = 0; q < 8; q++) {
                hh[q] = __float2bfloat16(vv[q]);
                ll[q] = __float2bfloat16(vv[q] - __bfloat162float(hh[q]));
            }
            *(uint4*)(Ah + row * APAD + cq) = *(uint4*)hh;
            *(uint4*)(Al + row * APAD + cq) = *(uint4*)ll;
        }
        // ---- B tile 16x128 from preconverted bf16: row = tid>>3, 16 cols each
        {
            int row = tid >> 3;
            int cb = (tid & 7) << 4;
            size_t go = (size_t)(k0 + row) * HID + bn + cb;
            *(uint4*)(Bh + row * BPAD + cb) = *(const uint4*)(g_Wh + go);
            *(uint4*)(Bh + row * BPAD + cb + 8) = *(const uint4*)(g_Wh + go + 8);
            *(uint4*)(Bl + row * BPAD + cb) = *(const uint4*)(g_Wl + go);
            *(uint4*)(Bl + row * BPAD + cb + 8) = *(const uint4*)(g_Wl + go + 8);
        }
        __syncthreads();

        wmma::fragment<wmma::matrix_b, 16, 16, 16, __nv_bfloat16, wmma::row_major> fbh[4], fbl[4];
#pragma unroll
        for (int j = 0; j < 4; j++) {
            wmma::load_matrix_sync(fbh[j], &Bh[wn * 64 + j * 16], BPAD);
            wmma::load_matrix_sync(fbl[j], &Bl[wn * 64 + j * 16], BPAD);
        }
#pragma unroll
        for (int i = 0; i < 2; i++) {
            wmma::fragment<wmma::matrix_a, 16, 16, 16, __nv_bfloat16, wmma::row_major> fah, fal;
            wmma::load_matrix_sync(fah, &Ah[(wm * 32 + i * 16) * APAD], APAD);
            wmma::load_matrix_sync(fal, &Al[(wm * 32 + i * 16) * APAD], APAD);
#pragma unroll
            for (int j = 0; j < 4; j++) {
                wmma::mma_sync(acc[i][j], fah, fbh[j], acc[i][j]);
                wmma::mma_sync(acc[i][j], fal, fbh[j], acc[i][j]);
                wmma::mma_sync(acc[i][j], fah, fbl[j], acc[i][j]);
            }
        }
        __syncthreads();
    }

#pragma unroll
    for (int i = 0; i < 2; i++) {
        int gr0 = bm + wm * 32 + i * 16;
        if (gr0 < NN) {  // NN % 16 == 0: tile fully in or out
#pragma unroll
            for (int j = 0; j < 4; j++)
                wmma::store_matrix_sync(g_hp + (size_t)gr0 * HID + bn + wn * 64 + j * 16,
                                        acc[i][j], HID, wmma::mem_row_major);
        }
    }
}

// ---------------- CSR build ----------------
__global__ void k_zero_cursor() {
    int i = blockIdx.x * blockDim.x + threadIdx.x;
    if (i < NN) g_cursor[i] = 0;
}

__global__ void k_count_deg(const int* __restrict__ dst) {
    int e = blockIdx.x * blockDim.x + threadIdx.x;
    if (e < NE) atomicAdd(&g_cursor[dst[e]], 1);
}

__global__ void k_scan1() {
    __shared__ int sh[1024];
    int i = blockIdx.x * 1024 + threadIdx.x;
    int v = (i < NN) ? g_cursor[i] : 0;
    sh[threadIdx.x] = v;
    __syncthreads();
    for (int off = 1; off < 1024; off <<= 1) {
        int t = (threadIdx.x >= off) ? sh[threadIdx.x - off] : 0;
        __syncthreads();
        sh[threadIdx.x] += t;
        __syncthreads();
    }
    if (i < NN) g_rowstart[i] = sh[threadIdx.x] - v;
    if (threadIdx.x == 1023) g_part[blockIdx.x] = sh[1023];
}

__global__ void k_scan2(int nparts) {
    __shared__ int sh[64];
    int t = threadIdx.x;
    int v0 = (t < nparts) ? g_part[t] : 0;
    sh[t] = v0;
    __syncthreads();
    for (int off = 1; off < 64; off <<= 1) {
        int v = (t >= off) ? sh[t - off] : 0;
        __syncthreads();
        sh[t] += v;
        __syncthreads();
    }
    if (t < nparts) g_part[t] = sh[t] - v0;  // exclusive
}

__global__ void k_scan3() {
    int i = blockIdx.x * blockDim.x + threadIdx.x;
    if (i < NN) {
        int v = g_rowstart[i] + g_part[i >> 10];
        g_rowstart[i] = v;
        g_cursor[i] = v;
    }
    if (i == 0) g_rowstart[NN] = NE;
}

__global__ void k_scatter(const int* __restrict__ dst) {
    int e = blockIdx.x * blockDim.x + threadIdx.x;
    if (e < NE) {
        int d = dst[e];
        int pos = atomicAdd(&g_cursor[d], 1);
        g_perm[pos] = e;
    }
}

// ---------------- input projection + LN + ELU -> g_bufA ----------------
__global__ void k_input_proj(const float* __restrict__ x, const float* __restrict__ Win,
                             const float* __restrict__ bin, const float* __restrict__ lg,
                             const float* __restrict__ lb) {
    int n = blockIdx.x;
    int c = threadIdx.x;  // 256
    __shared__ float xs[NDIM];
    __shared__ float s1[256], s2[256];
    if (c < NDIM) xs[c] = x[n * NDIM + c];
    __syncthreads();
    float v = bin[c];
#pragma unroll
    for (int k = 0; k < NDIM; k++) v += xs[k] * Win[k * HID + c];
    s1[c] = v;
    s2[c] = v * v;
    __syncthreads();
    for (int off = 128; off > 0; off >>= 1) {
        if (c < off) { s1[c] += s1[c + off]; s2[c] += s2[c + off]; }
        __syncthreads();
    }
    float mean = s1[0] * (1.f / HID);
    float var = s2[0] * (1.f / HID) - mean * mean;
    float rs = rsqrtf(var + 1e-5f);
    float y = (v - mean) * rs * lg[c] + lb[c];
    g_bufA[n * HID + c] = elu(y);
}

// ---------------- per-layer tiny coef ----------------
__global__ void k_edge_coef(const float* __restrict__ We, const float* __restrict__ ae) {
    int w = threadIdx.x >> 5;
    int lane = threadIdx.x & 31;
    if (w >= EDIM * NHEADS) return;
    int k = w >> 2, h = w & 3;
    const float* wrow = We + k * HID + h * HD;
    const float* arow = ae + h * HD;
    float v = wrow[lane] * arow[lane] + wrow[lane + 32] * arow[lane + 32];
#pragma unroll
    for (int off = 16; off > 0; off >>= 1) v += __shfl_down_sync(0xffffffffu, v, off);
    if (lane == 0) g_coef[k * NHEADS + h] = v;
}

// ---------------- per-(node,head) attention dots on g_hp ----------------
__global__ void k_sdots(const float* __restrict__ a_s, const float* __restrict__ a_d) {
    int w = (blockIdx.x * blockDim.x + threadIdx.x) >> 5;
    int lane = threadIdx.x & 31;
    if (w >= NN * NHEADS) return;
    int n = w >> 2, h = w & 3;
    const float* row = g_hp + n * HID + h * HD;
    float r0 = row[lane], r1 = row[lane + 32];
    float v1 = r0 * a_s[h * HD + lane] + r1 * a_s[h * HD + lane + 32];
    float v2 = r0 * a_d[h * HD + lane] + r1 * a_d[h * HD + lane + 32];
#pragma unroll
    for (int off = 16; off > 0; off >>= 1) {
        v1 += __shfl_down_sync(0xffffffffu, v1, off);
        v2 += __shfl_down_sync(0xffffffffu, v2, off);
    }
    if (lane == 0) { g_ssrc[w] = v1; g_sdst[w] = v2; }
}

// ---------------- fused: edge logits + per-node softmax stats (warp-per-node) ----------------
__global__ void k_node_stats(const int* __restrict__ src, const float* __restrict__ ea) {
    int w = (blockIdx.x * blockDim.x + threadIdx.x) >> 5;
    int lane = threadIdx.x & 31;
    if (w >= NN) return;
    int s0 = g_rowstart[w], s1 = g_rowstart[w + 1];

    // broadcast per-node dst-dot and coef
    float4 dv = *(const float4*)&g_sdst[w * NHEADS];
    float c00 = g_coef[0], c01 = g_coef[1], c02 = g_coef[2], c03 = g_coef[3];
    float c10 = g_coef[4], c11 = g_coef[5], c12 = g_coef[6], c13 = g_coef[7];
    float c20 = g_coef[8], c21 = g_coef[9], c22 = g_coef[10], c23 = g_coef[11];

    // pass 1: compute logits, write them, track max
    float4 mx = make_float4(-3.4e38f, -3.4e38f, -3.4e38f, -3.4e38f);
    for (int j = s0 + lane; j < s1; j += 32) {
        int e = g_perm[j];
        int s = src[e];
        float4 sv = *(const float4*)&g_ssrc[s * NHEADS];
        float a0 = ea[e * 3 + 0], a1 = ea[e * 3 + 1], a2 = ea[e * 3 + 2];
        float4 lg;
        lg.x = sv.x + dv.x + a0 * c00 + a1 * c10 + a2 * c20;
        lg.y = sv.y + dv.y + a0 * c01 + a1 * c11 + a2 * c21;
        lg.z = sv.z + dv.z + a0 * c02 + a1 * c12 + a2 * c22;
        lg.w = sv.w + dv.w + a0 * c03 + a1 * c13 + a2 * c23;
        lg.x = lg.x > 0.f ? lg.x : NEG_SLOPE * lg.x;
        lg.y = lg.y > 0.f ? lg.y : NEG_SLOPE * lg.y;
        lg.z = lg.z > 0.f ? lg.z : NEG_SLOPE * lg.z;
        lg.w = lg.w > 0.f ? lg.w : NEG_SLOPE * lg.w;
        *(float4*)&g_logit[e * NHEADS] = lg;
        mx.x = fmaxf(mx.x, lg.x); mx.y = fmaxf(mx.y, lg.y);
        mx.z = fmaxf(mx.z, lg.z); mx.w = fmaxf(mx.w, lg.w);
    }
#pragma unroll
    for (int off = 16; off > 0; off >>= 1) {
        mx.x = fmaxf(mx.x, __shfl_xor_sync(0xffffffffu, mx.x, off));
        mx.y = fmaxf(mx.y, __shfl_xor_sync(0xffffffffu, mx.y, off));
        mx.z = fmaxf(mx.z, __shfl_xor_sync(0xffffffffu, mx.z, off));
        mx.w = fmaxf(mx.w, __shfl_xor_sync(0xffffffffu, mx.w, off));
    }
    if (s0 == s1) mx = make_float4(0.f, 0.f, 0.f, 0.f);

    // pass 2: sum of exp (logits are L2-hot)
    float4 den = make_float4(0.f, 0.f, 0.f, 0.f);
    for (int j = s0 + lane; j < s1; j += 32) {
        int e = g_perm[j];
        float4 lg = *(const float4*)&g_logit[e * NHEADS];
        den.x += expf(lg.x - mx.x); den.y += expf(lg.y - mx.y);
        den.z += expf(lg.z - mx.z); den.w += expf(lg.w - mx.w);
    }
#pragma unroll
    for (int off = 16; off > 0; off >>= 1) {
        den.x += __shfl_xor_sync(0xffffffffu, den.x, off);
        den.y += __shfl_xor_sync(0xffffffffu, den.y, off);
        den.z += __shfl_xor_sync(0xffffffffu, den.z, off);
        den.w += __shfl_xor_sync(0xffffffffu, den.w, off);
    }
    if (lane == 0) {
        *(float4*)&g_m[w * NHEADS] = mx;
        float4 inv;
        inv.x = 1.f / fmaxf(den.x, 1e-16f);
        inv.y = 1.f / fmaxf(den.y, 1e-16f);
        inv.z = 1.f / fmaxf(den.z, 1e-16f);
        inv.w = 1.f / fmaxf(den.w, 1e-16f);
        *(float4*)&g_invden[w * NHEADS] = inv;
    }
}

// ---------------- staged aggregation (alpha fused): 4 nodes/block, 64 threads/node ----------------
#define ECH 64
__global__ void __launch_bounds__(256) k_aggregate(int insel, int outsel,
                                                   const int* __restrict__ src) {
    const float* hin = selbuf(insel);
    float* hout = selbuf(outsel);
    __shared__ int s_src[4][ECH];
    __shared__ float s_al[4][ECH * 4];
    __shared__ int s_deg[4];

    int tid = threadIdx.x;
    int slot = tid >> 6;
    int lt = tid & 63;
    int n = blockIdx.x * 4 + slot;   // NN % 4 == 0

    int s0 = g_rowstart[n], s1 = g_rowstart[n + 1];
    int deg = s1 - s0;
    if (lt == 0) s_deg[slot] = deg;
    float4 m4 = *(const float4*)&g_m[n * NHEADS];
    float4 iv4 = *(const float4*)&g_invden[n * NHEADS];
    __syncthreads();
    int maxdeg = max(max(s_deg[0], s_deg[1]), max(s_deg[2], s_deg[3]));

    int h = lt >> 4;                 // head for cols [lt*4, lt*4+4)
    float4 acc = make_float4(0.f, 0.f, 0.f, 0.f);

    for (int base = 0; base < maxdeg; base += ECH) {
        int cnt = min(ECH, deg - base);
        if (lt < cnt) {
            int e = g_perm[s0 + base + lt];
            s_src[slot][lt] = src[e];
            float4 lg = *(const float4*)&g_logit[e * NHEADS];
            float4 a;
            a.x = expf(lg.x - m4.x) * iv4.x;
            a.y = expf(lg.y - m4.y) * iv4.y;
            a.z = expf(lg.z - m4.z) * iv4.z;
            a.w = expf(lg.w - m4.w) * iv4.w;
            *(float4*)&s_al[slot][lt * 4] = a;
        }
        __syncthreads();
#pragma unroll 4
        for (int j = 0; j < cnt; j++) {
            int s = s_src[slot][j];
            float a = s_al[slot][j * 4 + h];
            float4 hv = *(const float4*)&g_hp[(size_t)s * HID + lt * 4];
            acc.x += a * hv.x; acc.y += a * hv.y;
            acc.z += a * hv.z; acc.w += a * hv.w;
        }
        __syncthreads();
    }

    float4 r = *(const float4*)&hin[(size_t)n * HID + lt * 4];
    float4 o;
    o.x = elu(acc.x + r.x); o.y = elu(acc.y + r.y);
    o.z = elu(acc.z + r.z); o.w = elu(acc.w + r.w);
    *(float4*)&hout[(size_t)n * HID + lt * 4] = o;
}

// ---------------- output LN + ELU, write node_emb ----------------
__global__ void k_ln_out(const float* __restrict__ lg, const float* __restrict__ lb,
                         float* __restrict__ outp, int fallback_sel) {
    float* o = outp ? outp : selbuf(fallback_sel);
    int n = blockIdx.x;
    int c = threadIdx.x;
    __shared__ float s1[256], s2[256];
    float v = g_hp[n * HID + c];
    s1[c] = v;
    s2[c] = v * v;
    __syncthreads();
    for (int off = 128; off > 0; off >>= 1) {
        if (c < off) { s1[c] += s1[c + off]; s2[c] += s2[c + off]; }
        __syncthreads();
    }
    float mean = s1[0] * (1.f / HID);
    float var = s2[0] * (1.f / HID) - mean * mean;
    float rs = rsqrtf(var + 1e-5f);
    float y = (v - mean) * rs * lg[c] + lb[c];
    o[n * HID + c] = elu(y);
}

// ---------------- pooling ----------------
__global__ void k_graph_starts(const int* __restrict__ batch) {
    int n = blockIdx.x * blockDim.x + threadIdx.x;
    if (n >= NN) return;
    int b = batch[n];
    int bp = (n == 0) ? -1 : batch[n - 1];
    for (int g = bp + 1; g <= b; g++) g_gstart[g] = n;
    if (n == NN - 1)
        for (int g = b + 1; g <= NG; g++) g_gstart[g] = NN;
}

__global__ void k_zero_float(float* p, int n) {
    int i = blockIdx.x * blockDim.x + threadIdx.x;
    if (i < n) p[i] = 0.f;
}

__global__ void k_pool_partial(const float* __restrict__ embp, int fallback_sel,
                               float* __restrict__ out) {
    const float* emb = embp ? embp : selbuf(fallback_sel);
    int g = blockIdx.x;
    int part = blockIdx.y;
    int c = threadIdx.x;
    int s = g_gstart[g], e = g_gstart[g + 1];
    int cnt = e - s;
    if (cnt <= 0) return;
    int chunk = (cnt + gridDim.y - 1) / gridDim.y;
    int ps = s + part * chunk;
    int pe = min(ps + chunk, e);
    if (ps >= pe) return;
    float acc = 0.f;
    for (int n = ps; n < pe; n++) acc += emb[n * HID + c];
    atomicAdd(&out[g * HID + c], acc);
}

__global__ void k_pool_final(float* __restrict__ out) {
    int g = blockIdx.x;
    int c = threadIdx.x;
    float cnt = (float)(g_gstart[g + 1] - g_gstart[g]);
    out[g * HID + c] /= fmaxf(cnt, 1.f);
}

// ---------------- launch ----------------
extern "C" void kernel_launch(void* const* d_in, const int* in_sizes, int n_in,
                              void* d_out, int out_size) {
    const float* x = (const float*)d_in[0];
    const int* edge_index = (const int*)d_in[1];   // int32
    const float* edge_attr = (const float*)d_in[2];
    const int* batch = (const int*)d_in[3];        // int32
    const float* x_W_in = (const float*)d_in[4];
    const float* b_in = (const float*)d_in[5];
    const float* ln_in_g = (const float*)d_in[6];
    const float* ln_in_b = (const float*)d_in[7];
    const float* W_gat = (const float*)d_in[8];
    const float* b_gat = (const float*)d_in[9];
    const float* W_e = (const float*)d_in[10];
    const float* a_src = (const float*)d_in[11];
    const float* a_dst = (const float*)d_in[12];
    const float* a_edge = (const float*)d_in[13];
    const float* W_out = (const float*)d_in[14];
    const float* b_out = (const float*)d_in[15];
    const float* ln_out_g = (const float*)d_in[16];
    const float* ln_out_b = (const float*)d_in[17];

    const int* src = edge_index;
    const int* dst = edge_index + NE;

    float* out = (float*)d_out;
    float* graph_out = nullptr;
    float* node_out = nullptr;
    if (out_size >= NG * HID + NN * HID) {
        graph_out = out;
        node_out = out + NG * HID;
    } else if (out_size >= NN * HID) {
        node_out = out;
    } else {
        graph_out = out;
    }

    const int EB = (NE + 255) / 256;
    const int NB = (NN + 255) / 256;
    const int NPARTS = (NN + 1023) / 1024;  // 49
    const int WS_B = (HID * HID + 255) / 256;
    dim3 gemm_grid((NN + GM - 1) / GM, HID / GN);  // (782, 2)

    // Launch order keeps layer-0 k_wmma_gemm at index 3 (ncu window).
    k_input_proj<<<NN, 256>>>(x, x_W_in, b_in, ln_in_g, ln_in_b);   // 0
    k_zero_cursor<<<NB, 256>>>();                                    // 1
    k_wsplit<<<WS_B, 256>>>(W_gat);                                  // 2 (layer 0 W)
    k_wmma_gemm<<<gemm_grid, 128>>>(0, b_gat);                       // 3 (layer 0)
    k_count_deg<<<EB, 256>>>(dst);                                   // 4
    k_scan1<<<NPARTS, 1024>>>();                                     // 5
    k_scan2<<<1, 64>>>(NPARTS);                                      // 6
    k_scan3<<<NB, 256>>>();                                          // 7
    k_scatter<<<EB, 256>>>(dst);                                     // 8

    int cur = 0;  // 0 = bufA, 1 = bufB
    for (int l = 0; l < NLAYERS; l++) {
        int nxt = 1 - cur;
        const float* Wl = W_gat + l * HID * HID;
        const float* bl = b_gat + l * HID;
        const float* Wel = W_e + l * EDIM * HID;
        const float* asl = a_src + l * NHEADS * HD;
        const float* adl = a_dst + l * NHEADS * HD;
        const float* ael = a_edge + l * NHEADS * HD;

        if (l > 0) {
            k_wsplit<<<WS_B, 256>>>(Wl);
            k_wmma_gemm<<<gemm_grid, 128>>>(cur, bl);
        }
        k_edge_coef<<<1, 384>>>(Wel, ael);
        k_sdots<<<(NN * NHEADS + 7) / 8, 256>>>(asl, adl);
        k_node_stats<<<(NN + 7) / 8, 256>>>(src, edge_attr);
        k_aggregate<<<NN / 4, 256>>>(cur, nxt, src);
        cur = nxt;
    }

    // ---- output projection + LN + ELU ----
    k_wsplit<<<WS_B, 256>>>(W_out);
    k_wmma_gemm<<<gemm_grid, 128>>>(cur, b_out);
    int fsel = 1 - cur;
    k_ln_out<<<NN, 256>>>(ln_out_g, ln_out_b, node_out, fsel);

    // ---- global mean pool ----
    if (graph_out) {
        k_graph_starts<<<NB, 256>>>(batch);
        k_zero_float<<<(NG * HID + 255) / 256, 256>>>(graph_out, NG * HID);
        dim3 pg(NG, 16);
        k_pool_partial<<<pg, 256>>>(node_out, fsel, graph_out);
        k_pool_final<<<NG, 256>>>(graph_out);
    }
}

// round 11
// speedup vs baseline: 1.0191x; 1.0191x over previous
#include <cuda_runtime.h>
#include <cuda_bf16.h>
#include <mma.h>
#include <math.h>
#include <stdint.h>

using namespace nvcuda;

#define NN 50000
#define NE 800000
#define NDIM 8
#define EDIM 3
#define HID 256
#define NHEADS 4
#define HD 64
#define NLAYERS 3
#define NG 64
#define NEG_SLOPE 0.2f

// ---------------- scratch (device globals; no allocation allowed) ----------------
__device__ float g_bufA[NN * HID];
__device__ float g_bufB[NN * HID];
__device__ float g_hp[NN * HID];
__device__ float g_logit[NE * NHEADS];   // raw leaky-relu'd logits (alpha computed in aggregate)
__device__ float g_ssrc[NN * NHEADS];
__device__ float g_sdst[NN * NHEADS];
__device__ float g_m[NN * NHEADS];
__device__ float g_invden[NN * NHEADS];
__device__ int   g_rowstart[NN + 1];
__device__ int   g_cursor[NN];
__device__ int   g_perm[NE];
__device__ int   g_part[64];
__device__ float g_coef[EDIM * NHEADS];
__device__ int   g_gstart[NG + 1];
__device__ __nv_bfloat16 g_Wh[HID * HID];
__device__ __nv_bfloat16 g_Wl[HID * HID];

__device__ __forceinline__ float* selbuf(int s) { return s ? g_bufB : g_bufA; }
__device__ __forceinline__ float elu(float x) { return x > 0.f ? x : expf(x) - 1.f; }

// ---------------- W -> bf16 hi/lo split (once per layer) ----------------
__global__ void k_wsplit(const float* __restrict__ W) {
    int i = blockIdx.x * blockDim.x + threadIdx.x;
    if (i >= HID * HID) return;
    float w = W[i];
    __nv_bfloat16 h = __float2bfloat16(w);
    g_Wh[i] = h;
    g_Wl[i] = __float2bfloat16(w - __bfloat162float(h));
}

// ================= pipelined wmma bf16-split GEMM: g_hp = selbuf(asel) @ W + bias =================
// Block: 64 rows x 128 cols, 4 warps (2x2). Double-buffered smem, 1 sync/iter.
#define GM 64
#define GN 128
#define APAD 24    // 48B stride
#define BPAD 136   // 272B stride

__global__ void __launch_bounds__(128, 3) k_wmma_gemm(int asel, const float* __restrict__ bias) {
    const float* A = selbuf(asel);
    __shared__ __nv_bfloat16 Ah[2][GM * APAD], Al[2][GM * APAD];
    __shared__ __nv_bfloat16 Bh[2][16 * BPAD], Bl[2][16 * BPAD];
    __shared__ float biasT[16 * GN];

    int tid = threadIdx.x;
    int wid = tid >> 5;
    int wm = wid >> 1;           // 0..1 -> 32-row slab
    int wn = wid & 1;            // 0..1 -> 64-col slab
    int bm = blockIdx.x * GM;
    int bn = blockIdx.y * GN;

    // A-load mapping: row = tid>>1 (0..63), 8 cols
    int arow = tid >> 1;
    int acq = (tid & 1) << 3;
    int agr = bm + arow;
    const float* aptr = (agr < NN) ? (A + (size_t)agr * HID + acq) : (const float*)0;
    // B-load mapping: row = tid>>3 (0..15), 16 cols
    int brow = tid >> 3;
    int bcb = (tid & 7) << 4;

    for (int i = tid; i < 16 * GN; i += 128) biasT[i] = bias[bn + (i & (GN - 1))];

    // staging registers
    float av[8];
    uint4 rbh0, rbh1, rbl0, rbl1;

    // ---- prologue: load + store k-chunk 0
    {
        if (aptr) {
            float4 v0 = *(const float4*)aptr;
            float4 v1 = *(const float4*)(aptr + 4);
            av[0] = v0.x; av[1] = v0.y; av[2] = v0.z; av[3] = v0.w;
            av[4] = v1.x; av[5] = v1.y; av[6] = v1.z; av[7] = v1.w;
        } else {
#pragma unroll
            for (int q = 0; q < 8; q++) av[q] = 0.f;
        }
        size_t go = (size_t)brow * HID + bn + bcb;
        rbh0 = *(const uint4*)(g_Wh + go); rbh1 = *(const uint4*)(g_Wh + go + 8);
        rbl0 = *(const uint4*)(g_Wl + go); rbl1 = *(const uint4*)(g_Wl + go + 8);

        __nv_bfloat16 hh[8], ll[8];
#pragma unroll
        for (int q = 0; q < 8; q++) {
            hh[q] = __float2bfloat16(av[q]);
            ll[q] = __float2bfloat16(av[q] - __bfloat162float(hh[q]));
        }
        *(uint4*)(&Ah[0][arow * APAD + acq]) = *(uint4*)hh;
        *(uint4*)(&Al[0][arow * APAD + acq]) = *(uint4*)ll;
        *(uint4*)(&Bh[0][brow * BPAD + bcb]) = rbh0;
        *(uint4*)(&Bh[0][brow * BPAD + bcb + 8]) = rbh1;
        *(uint4*)(&Bl[0][brow * BPAD + bcb]) = rbl0;
        *(uint4*)(&Bl[0][brow * BPAD + bcb + 8]) = rbl1;
    }
    __syncthreads();

    wmma::fragment<wmma::accumulator, 16, 16, 16, float> acc[2][4];
#pragma unroll
    for (int i = 0; i < 2; i++)
#pragma unroll
        for (int j = 0; j < 4; j++)
            wmma::load_matrix_sync(acc[i][j], &biasT[wn * 64 + j * 16], GN, wmma::mem_row_major);

    for (int kk = 0; kk < 16; kk++) {
        int cur = kk & 1;
        bool has_next = (kk < 15);

        // issue next-chunk global loads (latency hidden under MMAs below)
        if (has_next) {
            int k0 = (kk + 1) << 4;
            if (aptr) {
                float4 v0 = *(const float4*)(aptr + k0);
                float4 v1 = *(const float4*)(aptr + k0 + 4);
                av[0] = v0.x; av[1] = v0.y; av[2] = v0.z; av[3] = v0.w;
                av[4] = v1.x; av[5] = v1.y; av[6] = v1.z; av[7] = v1.w;
            }
            size_t go = (size_t)(k0 + brow) * HID + bn + bcb;
            rbh0 = *(const uint4*)(g_Wh + go); rbh1 = *(const uint4*)(g_Wh + go + 8);
            rbl0 = *(const uint4*)(g_Wl + go); rbl1 = *(const uint4*)(g_Wl + go + 8);
        }

        // compute on buffer `cur`
        wmma::fragment<wmma::matrix_b, 16, 16, 16, __nv_bfloat16, wmma::row_major> fbh[4], fbl[4];
#pragma unroll
        for (int j = 0; j < 4; j++) {
            wmma::load_matrix_sync(fbh[j], &Bh[cur][wn * 64 + j * 16], BPAD);
            wmma::load_matrix_sync(fbl[j], &Bl[cur][wn * 64 + j * 16], BPAD);
        }
#pragma unroll
        for (int i = 0; i < 2; i++) {
            wmma::fragment<wmma::matrix_a, 16, 16, 16, __nv_bfloat16, wmma::row_major> fah, fal;
            wmma::load_matrix_sync(fah, &Ah[cur][(wm * 32 + i * 16) * APAD], APAD);
            wmma::load_matrix_sync(fal, &Al[cur][(wm * 32 + i * 16) * APAD], APAD);
#pragma unroll
            for (int j = 0; j < 4; j++) {
                wmma::mma_sync(acc[i][j], fah, fbh[j], acc[i][j]);
                wmma::mma_sync(acc[i][j], fal, fbh[j], acc[i][j]);
                wmma::mma_sync(acc[i][j], fah, fbl[j], acc[i][j]);
            }
        }

        // convert + store next chunk into the other buffer
        if (has_next) {
            int nxt = 1 - cur;
            __nv_bfloat16 hh[8], ll[8];
#pragma unroll
            for (int q = 0; q < 8; q++) {
                hh[q] = __float2bfloat16(av[q]);
                ll[q] = __float2bfloat16(av[q] - __bfloat162float(hh[q]));
            }
            *(uint4*)(&Ah[nxt][arow * APAD + acq]) = *(uint4*)hh;
            *(uint4*)(&Al[nxt][arow * APAD + acq]) = *(uint4*)ll;
            *(uint4*)(&Bh[nxt][brow * BPAD + bcb]) = rbh0;
            *(uint4*)(&Bh[nxt][brow * BPAD + bcb + 8]) = rbh1;
            *(uint4*)(&Bl[nxt][brow * BPAD + bcb]) = rbl0;
            *(uint4*)(&Bl[nxt][brow * BPAD + bcb + 8]) = rbl1;
            __syncthreads();
        }
    }

#pragma unroll
    for (int i = 0; i < 2; i++) {
        int gr0 = bm + wm * 32 + i * 16;
        if (gr0 < NN) {  // NN % 16 == 0: tile fully in or out
#pragma unroll
            for (int j = 0; j < 4; j++)
                wmma::store_matrix_sync(g_hp + (size_t)gr0 * HID + bn + wn * 64 + j * 16,
                                        acc[i][j], HID, wmma::mem_row_major);
        }
    }
}

// ---------------- CSR build ----------------
__global__ void k_zero_cursor() {
    int i = blockIdx.x * blockDim.x + threadIdx.x;
    if (i < NN) g_cursor[i] = 0;
}

__global__ void k_count_deg(const int* __restrict__ dst) {
    int e = blockIdx.x * blockDim.x + threadIdx.x;
    if (e < NE) atomicAdd(&g_cursor[dst[e]], 1);
}

__global__ void k_scan1() {
    __shared__ int sh[1024];
    int i = blockIdx.x * 1024 + threadIdx.x;
    int v = (i < NN) ? g_cursor[i] : 0;
    sh[threadIdx.x] = v;
    __syncthreads();
    for (int off = 1; off < 1024; off <<= 1) {
        int t = (threadIdx.x >= off) ? sh[threadIdx.x - off] : 0;
        __syncthreads();
        sh[threadIdx.x] += t;
        __syncthreads();
    }
    if (i < NN) g_rowstart[i] = sh[threadIdx.x] - v;
    if (threadIdx.x == 1023) g_part[blockIdx.x] = sh[1023];
}

__global__ void k_scan2(int nparts) {
    __shared__ int sh[64];
    int t = threadIdx.x;
    int v0 = (t < nparts) ? g_part[t] : 0;
    sh[t] = v0;
    __syncthreads();
    for (int off = 1; off < 64; off <<= 1) {
        int v = (t >= off) ? sh[t - off] : 0;
        __syncthreads();
        sh[t] += v;
        __syncthreads();
    }
    if (t < nparts) g_part[t] = sh[t] - v0;  // exclusive
}

__global__ void k_scan3() {
    int i = blockIdx.x * blockDim.x + threadIdx.x;
    if (i < NN) {
        int v = g_rowstart[i] + g_part[i >> 10];
        g_rowstart[i] = v;
        g_cursor[i] = v;
    }
    if (i == 0) g_rowstart[NN] = NE;
}

__global__ void k_scatter(const int* __restrict__ dst) {
    int e = blockIdx.x * blockDim.x + threadIdx.x;
    if (e < NE) {
        int d = dst[e];
        int pos = atomicAdd(&g_cursor[d], 1);
        g_perm[pos] = e;
    }
}

// ---------------- input projection + LN + ELU -> g_bufA ----------------
__global__ void k_input_proj(const float* __restrict__ x, const float* __restrict__ Win,
                             const float* __restrict__ bin, const float* __restrict__ lg,
                             const float* __restrict__ lb) {
    int n = blockIdx.x;
    int c = threadIdx.x;  // 256
    __shared__ float xs[NDIM];
    __shared__ float s1[256], s2[256];
    if (c < NDIM) xs[c] = x[n * NDIM + c];
    __syncthreads();
    float v = bin[c];
#pragma unroll
    for (int k = 0; k < NDIM; k++) v += xs[k] * Win[k * HID + c];
    s1[c] = v;
    s2[c] = v * v;
    __syncthreads();
    for (int off = 128; off > 0; off >>= 1) {
        if (c < off) { s1[c] += s1[c + off]; s2[c] += s2[c + off]; }
        __syncthreads();
    }
    float mean = s1[0] * (1.f / HID);
    float var = s2[0] * (1.f / HID) - mean * mean;
    float rs = rsqrtf(var + 1e-5f);
    float y = (v - mean) * rs * lg[c] + lb[c];
    g_bufA[n * HID + c] = elu(y);
}

// ---------------- per-layer tiny coef ----------------
__global__ void k_edge_coef(const float* __restrict__ We, const float* __restrict__ ae) {
    int w = threadIdx.x >> 5;
    int lane = threadIdx.x & 31;
    if (w >= EDIM * NHEADS) return;
    int k = w >> 2, h = w & 3;
    const float* wrow = We + k * HID + h * HD;
    const float* arow = ae + h * HD;
    float v = wrow[lane] * arow[lane] + wrow[lane + 32] * arow[lane + 32];
#pragma unroll
    for (int off = 16; off > 0; off >>= 1) v += __shfl_down_sync(0xffffffffu, v, off);
    if (lane == 0) g_coef[k * NHEADS + h] = v;
}

// ---------------- per-(node,head) attention dots on g_hp ----------------
__global__ void k_sdots(const float* __restrict__ a_s, const float* __restrict__ a_d) {
    int w = (blockIdx.x * blockDim.x + threadIdx.x) >> 5;
    int lane = threadIdx.x & 31;
    if (w >= NN * NHEADS) return;
    int n = w >> 2, h = w & 3;
    const float* row = g_hp + n * HID + h * HD;
    float r0 = row[lane], r1 = row[lane + 32];
    float v1 = r0 * a_s[h * HD + lane] + r1 * a_s[h * HD + lane + 32];
    float v2 = r0 * a_d[h * HD + lane] + r1 * a_d[h * HD + lane + 32];
#pragma unroll
    for (int off = 16; off > 0; off >>= 1) {
        v1 += __shfl_down_sync(0xffffffffu, v1, off);
        v2 += __shfl_down_sync(0xffffffffu, v2, off);
    }
    if (lane == 0) { g_ssrc[w] = v1; g_sdst[w] = v2; }
}

// ---------------- edge logits (leaky-relu'd), edge-parallel coalesced ----------------
__global__ void k_edge_logits(const int* __restrict__ src, const int* __restrict__ dst,
                              const float* __restrict__ ea) {
    int e = blockIdx.x * blockDim.x + threadIdx.x;
    if (e >= NE) return;
    int s = src[e], d = dst[e];
    float a0 = ea[e * 3 + 0], a1 = ea[e * 3 + 1], a2 = ea[e * 3 + 2];
    float4 sv = *(const float4*)&g_ssrc[s * NHEADS];
    float4 dv = *(const float4*)&g_sdst[d * NHEADS];
    float4 out;
    float* o = (float*)&out;
    const float* ss = (const float*)&sv;
    const float* dd = (const float*)&dv;
#pragma unroll
    for (int h = 0; h < NHEADS; h++) {
        float lg = ss[h] + dd[h] +
                   a0 * g_coef[0 * NHEADS + h] + a1 * g_coef[1 * NHEADS + h] +
                   a2 * g_coef[2 * NHEADS + h];
        o[h] = lg > 0.f ? lg : NEG_SLOPE * lg;
    }
    *(float4*)&g_logit[e * NHEADS] = out;
}

// ---------------- per-node softmax stats: warp-per-node ----------------
__global__ void k_node_stats() {
    int w = (blockIdx.x * blockDim.x + threadIdx.x) >> 5;
    int lane = threadIdx.x & 31;
    if (w >= NN) return;
    int s0 = g_rowstart[w], s1 = g_rowstart[w + 1];

    float4 mx = make_float4(-3.4e38f, -3.4e38f, -3.4e38f, -3.4e38f);
    for (int j = s0 + lane; j < s1; j += 32) {
        int e = g_perm[j];
        float4 lg = *(const float4*)&g_logit[e * NHEADS];
        mx.x = fmaxf(mx.x, lg.x); mx.y = fmaxf(mx.y, lg.y);
        mx.z = fmaxf(mx.z, lg.z); mx.w = fmaxf(mx.w, lg.w);
    }
#pragma unroll
    for (int off = 16; off > 0; off >>= 1) {
        mx.x = fmaxf(mx.x, __shfl_xor_sync(0xffffffffu, mx.x, off));
        mx.y = fmaxf(mx.y, __shfl_xor_sync(0xffffffffu, mx.y, off));
        mx.z = fmaxf(mx.z, __shfl_xor_sync(0xffffffffu, mx.z, off));
        mx.w = fmaxf(mx.w, __shfl_xor_sync(0xffffffffu, mx.w, off));
    }
    if (s0 == s1) mx = make_float4(0.f, 0.f, 0.f, 0.f);

    float4 den = make_float4(0.f, 0.f, 0.f, 0.f);
    for (int j = s0 + lane; j < s1; j += 32) {
        int e = g_perm[j];
        float4 lg = *(const float4*)&g_logit[e * NHEADS];
        den.x += expf(lg.x - mx.x); den.y += expf(lg.y - mx.y);
        den.z += expf(lg.z - mx.z); den.w += expf(lg.w - mx.w);
    }
#pragma unroll
    for (int off = 16; off > 0; off >>= 1) {
        den.x += __shfl_xor_sync(0xffffffffu, den.x, off);
        den.y += __shfl_xor_sync(0xffffffffu, den.y, off);
        den.z += __shfl_xor_sync(0xffffffffu, den.z, off);
        den.w += __shfl_xor_sync(0xffffffffu, den.w, off);
    }
    if (lane == 0) {
        *(float4*)&g_m[w * NHEADS] = mx;
        float4 inv;
        inv.x = 1.f / fmaxf(den.x, 1e-16f);
        inv.y = 1.f / fmaxf(den.y, 1e-16f);
        inv.z = 1.f / fmaxf(den.z, 1e-16f);
        inv.w = 1.f / fmaxf(den.w, 1e-16f);
        *(float4*)&g_invden[w * NHEADS] = inv;
    }
}

// ---------------- staged aggregation (alpha fused): 4 nodes/block, 64 threads/node ----------------
#define ECH 64
__global__ void __launch_bounds__(256) k_aggregate(int insel, int outsel,
                                                   const int* __restrict__ src) {
    const float* hin = selbuf(insel);
    float* hout = selbuf(outsel);
    __shared__ int s_src[4][ECH];
    __shared__ float s_al[4][ECH * 4];
    __shared__ int s_deg[4];

    int tid = threadIdx.x;
    int slot = tid >> 6;
    int lt = tid & 63;
    int n = blockIdx.x * 4 + slot;   // NN % 4 == 0

    int s0 = g_rowstart[n], s1 = g_rowstart[n + 1];
    int deg = s1 - s0;
    if (lt == 0) s_deg[slot] = deg;
    float4 m4 = *(const float4*)&g_m[n * NHEADS];
    float4 iv4 = *(const float4*)&g_invden[n * NHEADS];
    __syncthreads();
    int maxdeg = max(max(s_deg[0], s_deg[1]), max(s_deg[2], s_deg[3]));

    int h = lt >> 4;                 // head for cols [lt*4, lt*4+4)
    float4 acc = make_float4(0.f, 0.f, 0.f, 0.f);

    for (int base = 0; base < maxdeg; base += ECH) {
        int cnt = min(ECH, deg - base);
        if (lt < cnt) {
            int e = g_perm[s0 + base + lt];
            s_src[slot][lt] = src[e];
            float4 lg = *(const float4*)&g_logit[e * NHEADS];
            float4 a;
            a.x = expf(lg.x - m4.x) * iv4.x;
            a.y = expf(lg.y - m4.y) * iv4.y;
            a.z = expf(lg.z - m4.z) * iv4.z;
            a.w = expf(lg.w - m4.w) * iv4.w;
            *(float4*)&s_al[slot][lt * 4] = a;
        }
        __syncthreads();
#pragma unroll 4
        for (int j = 0; j < cnt; j++) {
            int s = s_src[slot][j];
            float a = s_al[slot][j * 4 + h];
            float4 hv = *(const float4*)&g_hp[(size_t)s * HID + lt * 4];
            acc.x += a * hv.x; acc.y += a * hv.y;
            acc.z += a * hv.z; acc.w += a * hv.w;
        }
        __syncthreads();
    }

    float4 r = *(const float4*)&hin[(size_t)n * HID + lt * 4];
    float4 o;
    o.x = elu(acc.x + r.x); o.y = elu(acc.y + r.y);
    o.z = elu(acc.z + r.z); o.w = elu(acc.w + r.w);
    *(float4*)&hout[(size_t)n * HID + lt * 4] = o;
}

// ---------------- output LN + ELU, write node_emb ----------------
__global__ void k_ln_out(const float* __restrict__ lg, const float* __restrict__ lb,
                         float* __restrict__ outp, int fallback_sel) {
    float* o = outp ? outp : selbuf(fallback_sel);
    int n = blockIdx.x;
    int c = threadIdx.x;
    __shared__ float s1[256], s2[256];
    float v = g_hp[n * HID + c];
    s1[c] = v;
    s2[c] = v * v;
    __syncthreads();
    for (int off = 128; off > 0; off >>= 1) {
        if (c < off) { s1[c] += s1[c + off]; s2[c] += s2[c + off]; }
        __syncthreads();
    }
    float mean = s1[0] * (1.f / HID);
    float var = s2[0] * (1.f / HID) - mean * mean;
    float rs = rsqrtf(var + 1e-5f);
    float y = (v - mean) * rs * lg[c] + lb[c];
    o[n * HID + c] = elu(y);
}

// ---------------- pooling ----------------
__global__ void k_graph_starts(const int* __restrict__ batch) {
    int n = blockIdx.x * blockDim.x + threadIdx.x;
    if (n >= NN) return;
    int b = batch[n];
    int bp = (n == 0) ? -1 : batch[n - 1];
    for (int g = bp + 1; g <= b; g++) g_gstart[g] = n;
    if (n == NN - 1)
        for (int g = b + 1; g <= NG; g++) g_gstart[g] = NN;
}

__global__ void k_zero_float(float* p, int n) {
    int i = blockIdx.x * blockDim.x + threadIdx.x;
    if (i < n) p[i] = 0.f;
}

__global__ void k_pool_partial(const float* __restrict__ embp, int fallback_sel,
                               float* __restrict__ out) {
    const float* emb = embp ? embp : selbuf(fallback_sel);
    int g = blockIdx.x;
    int part = blockIdx.y;
    int c = threadIdx.x;
    int s = g_gstart[g], e = g_gstart[g + 1];
    int cnt = e - s;
    if (cnt <= 0) return;
    int chunk = (cnt + gridDim.y - 1) / gridDim.y;
    int ps = s + part * chunk;
    int pe = min(ps + chunk, e);
    if (ps >= pe) return;
    float acc = 0.f;
    for (int n = ps; n < pe; n++) acc += emb[n * HID + c];
    atomicAdd(&out[g * HID + c], acc);
}

__global__ void k_pool_final(float* __restrict__ out) {
    int g = blockIdx.x;
    int c = threadIdx.x;
    float cnt = (float)(g_gstart[g + 1] - g_gstart[g]);
    out[g * HID + c] /= fmaxf(cnt, 1.f);
}

// ---------------- launch ----------------
extern "C" void kernel_launch(void* const* d_in, const int* in_sizes, int n_in,
                              void* d_out, int out_size) {
    const float* x = (const float*)d_in[0];
    const int* edge_index = (const int*)d_in[1];   // int32
    const float* edge_attr = (const float*)d_in[2];
    const int* batch = (const int*)d_in[3];        // int32
    const float* x_W_in = (const float*)d_in[4];
    const float* b_in = (const float*)d_in[5];
    const float* ln_in_g = (const float*)d_in[6];
    const float* ln_in_b = (const float*)d_in[7];
    const float* W_gat = (const float*)d_in[8];
    const float* b_gat = (const float*)d_in[9];
    const float* W_e = (const float*)d_in[10];
    const float* a_src = (const float*)d_in[11];
    const float* a_dst = (const float*)d_in[12];
    const float* a_edge = (const float*)d_in[13];
    const float* W_out = (const float*)d_in[14];
    const float* b_out = (const float*)d_in[15];
    const float* ln_out_g = (const float*)d_in[16];
    const float* ln_out_b = (const float*)d_in[17];

    const int* src = edge_index;
    const int* dst = edge_index + NE;

    float* out = (float*)d_out;
    float* graph_out = nullptr;
    float* node_out = nullptr;
    if (out_size >= NG * HID + NN * HID) {
        graph_out = out;
        node_out = out + NG * HID;
    } else if (out_size >= NN * HID) {
        node_out = out;
    } else {
        graph_out = out;
    }

    const int EB = (NE + 255) / 256;
    const int NB = (NN + 255) / 256;
    const int NPARTS = (NN + 1023) / 1024;  // 49
    const int WS_B = (HID * HID + 255) / 256;
    dim3 gemm_grid((NN + GM - 1) / GM, HID / GN);  // (782, 2)

    // Launch order keeps layer-0 k_wmma_gemm at index 3 (ncu window).
    k_input_proj<<<NN, 256>>>(x, x_W_in, b_in, ln_in_g, ln_in_b);   // 0
    k_zero_cursor<<<NB, 256>>>();                                    // 1
    k_wsplit<<<WS_B, 256>>>(W_gat);                                  // 2 (layer 0 W)
    k_wmma_gemm<<<gemm_grid, 128>>>(0, b_gat);                       // 3 (layer 0)
    k_count_deg<<<EB, 256>>>(dst);                                   // 4
    k_scan1<<<NPARTS, 1024>>>();                                     // 5
    k_scan2<<<1, 64>>>(NPARTS);                                      // 6
    k_scan3<<<NB, 256>>>();                                          // 7
    k_scatter<<<EB, 256>>>(dst);                                     // 8

    int cur = 0;  // 0 = bufA, 1 = bufB
    for (int l = 0; l < NLAYERS; l++) {
        int nxt = 1 - cur;
        const float* Wl = W_gat + l * HID * HID;
        const float* bl = b_gat + l * HID;
        const float* Wel = W_e + l * EDIM * HID;
        const float* asl = a_src + l * NHEADS * HD;
        const float* adl = a_dst + l * NHEADS * HD;
        const float* ael = a_edge + l * NHEADS * HD;

        if (l > 0) {
            k_wsplit<<<WS_B, 256>>>(Wl);
            k_wmma_gemm<<<gemm_grid, 128>>>(cur, bl);
        }
        k_edge_coef<<<1, 384>>>(Wel, ael);
        k_sdots<<<(NN * NHEADS + 7) / 8, 256>>>(asl, adl);
        k_edge_logits<<<EB, 256>>>(src, dst, edge_attr);
        k_node_stats<<<(NN + 7) / 8, 256>>>();
        k_aggregate<<<NN / 4, 256>>>(cur, nxt, src);
        cur = nxt;
    }

    // ---- output projection + LN + ELU ----
    k_wsplit<<<WS_B, 256>>>(W_out);
    k_wmma_gemm<<<gemm_grid, 128>>>(cur, b_out);
    int fsel = 1 - cur;
    k_ln_out<<<NN, 256>>>(ln_out_g, ln_out_b, node_out, fsel);

    // ---- global mean pool ----
    if (graph_out) {
        k_graph_starts<<<NB, 256>>>(batch);
        k_zero_float<<<(NG * HID + 255) / 256, 256>>>(graph_out, NG * HID);
        dim3 pg(NG, 16);
        k_pool_partial<<<pg, 256>>>(node_out, fsel, graph_out);
        k_pool_final<<<NG, 256>>>(graph_out);
    }
}